// round 1
// baseline (speedup 1.0000x reference)
#include <cuda_runtime.h>
#include <math.h>

#define Bc 2
#define Sc 2048
#define Tc 8
#define Cc 128
#define Kc 16
#define Hc 4
#define Dc 32
#define Fc 130        // C+2
#define F2c 132       // padded row for smem
#define BTc (Bc*Tc)   // 16
#define Nc (BTc*Sc)   // 32768
#define Uc (Hc*Fc)    // 520

// ---- scratch (no allocations allowed; __device__ globals) ----
__device__ float g_Wu[Cc*Uc];             // [c][h*F+f]  (scale 1/sqrt(D) folded in)
__device__ float g_WoT[Uc*Cc];            // [h*F+f][c']
__device__ float g_U[(size_t)Nc*Uc];      // 68 MB
__device__ float g_NB[(size_t)Nc*Uc];     // 68 MB
__device__ int   g_is64;

// ---------------------------------------------------------------------------
// k_detect: spatial_idx may be int32 (jax without x64) or int64.
// Values are in [0, 2048). If the buffer is int64 little-endian, every odd
// 32-bit word is 0. Deterministic given inputs.
// ---------------------------------------------------------------------------
__global__ void k_detect(const unsigned int* __restrict__ p) {
    __shared__ int any;
    if (threadIdx.x == 0) any = 0;
    __syncthreads();
    for (int i = threadIdx.x; i < 4096; i += blockDim.x)
        if (p[2*i + 1] != 0u) any = 1;
    __syncthreads();
    if (threadIdx.x == 0) g_is64 = (any == 0) ? 1 : 0;
}

// ---------------------------------------------------------------------------
// k0: combined weight matrices.
//   W_u[c][h*F+f]  = (1/sqrt(D)) * sum_d Wq[h*D+d, c] * Wk[h*D+d, f]
//   W_oT[h*F+f][c'] =             sum_d Wp[c', h*D+d] * Wv[h*D+d, f]
// ---------------------------------------------------------------------------
__global__ void k0_combine(const float* __restrict__ Wq, const float* __restrict__ Wk,
                           const float* __restrict__ Wv, const float* __restrict__ Wp) {
    int i = blockIdx.x * blockDim.x + threadIdx.x;
    if (i >= Cc*Uc) return;
    int c = i / Uc;
    int j = i % Uc;
    int h = j / Fc;
    int f = j % Fc;
    float su = 0.f, so = 0.f;
    #pragma unroll
    for (int d = 0; d < Dc; d++) {
        int hd = h*Dc + d;
        su = fmaf(Wq[hd*Cc + c], Wk[hd*(Cc+2) + f], su);
        so = fmaf(Wp[c*Cc + hd], Wv[hd*(Cc+2) + f], so);
    }
    g_Wu[c*Uc + j]  = su * rsqrtf((float)Dc);
    g_WoT[j*Cc + c] = so;
}

// ---------------------------------------------------------------------------
// k1: U[n][j] = sum_c X_[n][c] * W_u[c][j]
// X_[n][c] = x[((b*S + s)*T + t)*C + c] with n = bt*S + s, bt = b*T + t.
// 32 rows per block, 544 threads (j = tid, j<520 active).
// ---------------------------------------------------------------------------
__global__ __launch_bounds__(544) void k1_u(const float* __restrict__ x) {
    __shared__ float4 xs4[32][32];   // 32 rows x 128 floats
    int base = blockIdx.x * 32;
    int bt = base / Sc;
    int s0 = base % Sc;
    int b = bt / Tc, t = bt % Tc;
    int tid = threadIdx.x;

    for (int idx = tid; idx < 1024; idx += 544) {
        int r = idx >> 5, c4 = idx & 31;
        const float4* src = (const float4*)(x + ((size_t)((b*Sc + s0 + r)*Tc + t)) * Cc);
        xs4[r][c4] = src[c4];
    }
    __syncthreads();

    int j = tid;
    if (j < Uc) {
        float acc[32];
        #pragma unroll
        for (int r = 0; r < 32; r++) acc[r] = 0.f;
        #pragma unroll 4
        for (int c4 = 0; c4 < 32; c4++) {
            float w0 = g_Wu[(c4*4 + 0)*Uc + j];
            float w1 = g_Wu[(c4*4 + 1)*Uc + j];
            float w2 = g_Wu[(c4*4 + 2)*Uc + j];
            float w3 = g_Wu[(c4*4 + 3)*Uc + j];
            #pragma unroll
            for (int r = 0; r < 32; r++) {
                float4 xv = xs4[r][c4];
                acc[r] = fmaf(xv.x, w0, acc[r]);
                acc[r] = fmaf(xv.y, w1, acc[r]);
                acc[r] = fmaf(xv.z, w2, acc[r]);
                acc[r] = fmaf(xv.w, w3, acc[r]);
            }
        }
        #pragma unroll
        for (int r = 0; r < 32; r++)
            g_U[(size_t)(base + r)*Uc + j] = acc[r];
    }
}

// ---------------------------------------------------------------------------
// k2: per (bt,s): gather K neighbors, logits, softmax, weighted neighbor sum.
// ---------------------------------------------------------------------------
__global__ __launch_bounds__(128) void k2_attn(const float* __restrict__ x,
                                               const void* __restrict__ sidx,
                                               const float* __restrict__ swgt,
                                               const float* __restrict__ ali,
                                               const float* __restrict__ dstp) {
    __shared__ __align__(16) float nb[Kc][F2c];  // K x 130 (padded)
    __shared__ float us[Hc][Fc];
    __shared__ float attn_s[Hc][Kc];

    int n = blockIdx.x;
    int bt = n / Sc;
    int b = bt / Tc, t = bt % Tc;
    int tid = threadIdx.x;

    // load u for this (bt,s)
    for (int i = tid; i < Uc; i += 128)
        us[i / Fc][i % Fc] = g_U[(size_t)n*Uc + i];

    // gather neighbors: 8 threads per k
    int k = tid >> 3, l8 = tid & 7;
    long long jn;
    if (g_is64) jn = ((const long long*)sidx)[(size_t)n*Kc + k];
    else        jn = (long long)((const int*)sidx)[(size_t)n*Kc + k];
    const float4* src = (const float4*)(x + ((size_t)((b*Sc + (int)jn)*Tc + t)) * Cc);
    #pragma unroll
    for (int q = 0; q < 4; q++) {
        int f4 = l8 + q*8;
        float4 v = src[f4];
        *((float4*)&nb[k][f4*4]) = v;
    }
    if (l8 == 0) {
        nb[k][128] = ali [(size_t)n*Kc + k];
        nb[k][129] = dstp[(size_t)n*Kc + k];
    }
    __syncthreads();

    // logits + softmax (64 threads: h = tid/16, k = tid%16)
    if (tid < Hc*Kc) {
        int h = tid >> 4, kk = tid & 15;
        float acc = 0.f;
        #pragma unroll 2
        for (int f = 0; f < Fc; f++)
            acc = fmaf(us[h][f], nb[kk][f], acc);
        float lg = acc + logf(swgt[(size_t)n*Kc + kk] + 1e-6f);
        float m = lg;
        #pragma unroll
        for (int o = 8; o >= 1; o >>= 1)
            m = fmaxf(m, __shfl_xor_sync(0xffffffffu, m, o, 16));
        float e = __expf(lg - m);
        float ssum = e;
        #pragma unroll
        for (int o = 8; o >= 1; o >>= 1)
            ssum += __shfl_xor_sync(0xffffffffu, ssum, o, 16);
        attn_s[h][kk] = e / ssum;
    }
    __syncthreads();

    // nbar[h][f] = sum_k attn[h][k] * nb[k][f]  -> NB[n][h*F+f]
    for (int i = tid; i < Uc; i += 128) {
        int h = i / Fc, f = i % Fc;
        float acc = 0.f;
        #pragma unroll
        for (int kk = 0; kk < Kc; kk++)
            acc = fmaf(attn_s[h][kk], nb[kk][f], acc);
        g_NB[(size_t)n*Uc + i] = acc;
    }
}

// ---------------------------------------------------------------------------
// k3: OUT[n][c'] = sum_j NB[n][j] * W_oT[j][c'] + bp[c'], scattered back to
// out[b,s,t,c'] layout. 16 rows per block, 128 threads (c' = tid).
// ---------------------------------------------------------------------------
__global__ __launch_bounds__(128) void k3_out(const float* __restrict__ bp,
                                              float* __restrict__ out) {
    __shared__ float4 nbs4[16][130];  // 16 rows x 520 floats
    int base = blockIdx.x * 16;
    int bt = base / Sc;
    int s0 = base % Sc;
    int b = bt / Tc, t = bt % Tc;
    int tid = threadIdx.x;

    for (int idx = tid; idx < 16*130; idx += 128) {
        int r = idx / 130, j4 = idx % 130;
        nbs4[r][j4] = ((const float4*)(g_NB + (size_t)(base + r)*Uc))[j4];
    }
    __syncthreads();

    int cp = tid;  // 0..127
    float acc[16];
    #pragma unroll
    for (int r = 0; r < 16; r++) acc[r] = 0.f;
    #pragma unroll 2
    for (int j4 = 0; j4 < 130; j4++) {
        float w0 = g_WoT[(j4*4 + 0)*Cc + cp];
        float w1 = g_WoT[(j4*4 + 1)*Cc + cp];
        float w2 = g_WoT[(j4*4 + 2)*Cc + cp];
        float w3 = g_WoT[(j4*4 + 3)*Cc + cp];
        #pragma unroll
        for (int r = 0; r < 16; r++) {
            float4 nv = nbs4[r][j4];
            acc[r] = fmaf(nv.x, w0, acc[r]);
            acc[r] = fmaf(nv.y, w1, acc[r]);
            acc[r] = fmaf(nv.z, w2, acc[r]);
            acc[r] = fmaf(nv.w, w3, acc[r]);
        }
    }
    float bias = bp[cp];
    #pragma unroll
    for (int r = 0; r < 16; r++) {
        int s = s0 + r;
        out[((size_t)((b*Sc + s)*Tc + t))*Cc + cp] = acc[r] + bias;
    }
}

// ---------------------------------------------------------------------------
extern "C" void kernel_launch(void* const* d_in, const int* in_sizes, int n_in,
                              void* d_out, int out_size) {
    const float* x    = (const float*)d_in[0];
    const void*  sidx = d_in[1];
    const float* swgt = (const float*)d_in[2];
    const float* ali  = (const float*)d_in[3];
    const float* dstp = (const float*)d_in[4];
    const float* Wq   = (const float*)d_in[5];
    const float* Wk   = (const float*)d_in[6];
    const float* Wv   = (const float*)d_in[7];
    const float* Wp   = (const float*)d_in[8];
    const float* bp   = (const float*)d_in[9];
    float* out = (float*)d_out;

    k_detect<<<1, 256>>>((const unsigned int*)sidx);
    k0_combine<<<(Cc*Uc + 255)/256, 256>>>(Wq, Wk, Wv, Wp);
    k1_u<<<Nc/32, 544>>>(x);
    k2_attn<<<Nc, 128>>>(x, sidx, swgt, ali, dstp);
    k3_out<<<Nc/16, 128>>>(bp, out);
}

// round 2
// speedup vs baseline: 1.0567x; 1.0567x over previous
#include <cuda_runtime.h>
#include <math.h>

#define Bc 2
#define Sc 2048
#define Tc 8
#define Cc 128
#define Kc 16
#define Hc 4
#define Dc 32
#define Fc 130        // C+2
#define F2c 132       // padded row for smem
#define BTc (Bc*Tc)   // 16
#define Nc (BTc*Sc)   // 32768
#define Uc (Hc*Fc)    // 520

typedef unsigned long long u64;

// ---- scratch (no allocations allowed; __device__ globals) ----
__device__ float g_Wu[Cc*Uc];             // [c][h*F+f]  (1/sqrt(D) folded in)
__device__ float g_WoT[Uc*Cc];            // [h*F+f][c']
__device__ float g_U[(size_t)Nc*Uc];      // 68 MB
__device__ float g_NB[(size_t)Nc*Uc];     // 68 MB
__device__ int   g_is64;

// packed fp32x2 helpers (sm_100+ f32x2 pipe: 2 MACs per instr)
__device__ __forceinline__ void fma2(u64& d, u64 a, u64 b) {
    asm("fma.rn.f32x2 %0, %1, %2, %0;" : "+l"(d) : "l"(a), "l"(b));
}
__device__ __forceinline__ u64 pack2(float lo, float hi) {
    u64 r;
    asm("mov.b64 %0, {%1, %2};" : "=l"(r) : "f"(lo), "f"(hi));
    return r;
}
__device__ __forceinline__ void unpack2(u64 v, float& lo, float& hi) {
    asm("mov.b64 {%0, %1}, %2;" : "=f"(lo), "=f"(hi) : "l"(v));
}

// ---------------------------------------------------------------------------
// k_detect: spatial_idx may be int32 or int64 (values < 2048 -> odd words 0).
// ---------------------------------------------------------------------------
__global__ void k_detect(const unsigned int* __restrict__ p) {
    __shared__ int any;
    if (threadIdx.x == 0) any = 0;
    __syncthreads();
    for (int i = threadIdx.x; i < 4096; i += blockDim.x)
        if (p[2*i + 1] != 0u) any = 1;
    __syncthreads();
    if (threadIdx.x == 0) g_is64 = (any == 0) ? 1 : 0;
}

// ---------------------------------------------------------------------------
// k0: combined weights.
//   W_u[c][h*F+f]   = (1/sqrt(D)) * sum_d Wq[h*D+d, c] * Wk[h*D+d, f]
//   W_oT[h*F+f][c'] =               sum_d Wp[c', h*D+d] * Wv[h*D+d, f]
// ---------------------------------------------------------------------------
__global__ void k0_combine(const float* __restrict__ Wq, const float* __restrict__ Wk,
                           const float* __restrict__ Wv, const float* __restrict__ Wp) {
    int i = blockIdx.x * blockDim.x + threadIdx.x;
    if (i >= Cc*Uc) return;
    int c = i / Uc;
    int j = i % Uc;
    int h = j / Fc;
    int f = j % Fc;
    float su = 0.f, so = 0.f;
    #pragma unroll
    for (int d = 0; d < Dc; d++) {
        int hd = h*Dc + d;
        su = fmaf(Wq[hd*Cc + c], Wk[hd*(Cc+2) + f], su);
        so = fmaf(Wp[c*Cc + hd], Wv[hd*(Cc+2) + f], so);
    }
    g_Wu[c*Uc + j]  = su * rsqrtf((float)Dc);
    g_WoT[j*Cc + c] = so;
}

// ---------------------------------------------------------------------------
// k1: U = X_ @ W_u. 32 rows/block packed as 16 row-pairs, 544 threads
// (j = tid < 520). Inner math in fma.rn.f32x2 (2 MACs/instr).
// ---------------------------------------------------------------------------
__global__ __launch_bounds__(544) void k1_u(const float* __restrict__ x) {
    __shared__ u64 xs2[Cc*16];   // [c][rp] pair = rows (2rp, 2rp+1); 16KB
    int base = blockIdx.x * 32;
    int bt = base / Sc;
    int s0 = base % Sc;
    int b = bt / Tc, t = bt % Tc;
    int tid = threadIdx.x;

    if (tid < 512) {
        int rp = tid & 15, c4 = tid >> 4;        // c4 in 0..31
        const float* r0 = x + ((size_t)((b*Sc + s0 + 2*rp)*Tc + t)) * Cc;
        const float* r1 = r0 + (size_t)Tc * Cc;  // next s
        float4 a = ((const float4*)r0)[c4];
        float4 bb = ((const float4*)r1)[c4];
        int c = 4*c4;
        xs2[(c+0)*16 + rp] = pack2(a.x, bb.x);
        xs2[(c+1)*16 + rp] = pack2(a.y, bb.y);
        xs2[(c+2)*16 + rp] = pack2(a.z, bb.z);
        xs2[(c+3)*16 + rp] = pack2(a.w, bb.w);
    }
    __syncthreads();

    int j = tid;
    if (j < Uc) {
        u64 acc[16];
        #pragma unroll
        for (int rp = 0; rp < 16; rp++) acc[rp] = pack2(0.f, 0.f);
        #pragma unroll 4
        for (int c = 0; c < Cc; c++) {
            float w = g_Wu[c*Uc + j];
            u64 wp = pack2(w, w);
            #pragma unroll
            for (int rp = 0; rp < 16; rp++)
                fma2(acc[rp], xs2[c*16 + rp], wp);
        }
        #pragma unroll
        for (int rp = 0; rp < 16; rp++) {
            float lo, hi;
            unpack2(acc[rp], lo, hi);
            g_U[(size_t)(base + 2*rp    )*Uc + j] = lo;
            g_U[(size_t)(base + 2*rp + 1)*Uc + j] = hi;
        }
    }
}

// ---------------------------------------------------------------------------
// k2: per (bt,s): gather K neighbors, logits, softmax, weighted neighbor sum.
// Restructured so each nb element is read ONCE per phase (4 heads amortized).
// ---------------------------------------------------------------------------
__global__ __launch_bounds__(128) void k2_attn(const float* __restrict__ x,
                                               const void* __restrict__ sidx,
                                               const float* __restrict__ swgt,
                                               const float* __restrict__ ali,
                                               const float* __restrict__ dstp) {
    __shared__ __align__(16) float nb[Kc][F2c];  // K x 130 (padded to 132)
    __shared__ __align__(16) float us[Uc];
    __shared__ float lg[Hc][Kc];
    __shared__ float attn_s[Hc][Kc];

    int n = blockIdx.x;
    int bt = n >> 11;                 // n / S
    int b = bt >> 3, t = bt & 7;
    int tid = threadIdx.x;

    // load u for this (bt,s): 520 floats = 130 float4
    for (int i = tid; i < Uc/4; i += 128)
        ((float4*)us)[i] = ((const float4*)(g_U + (size_t)n*Uc))[i];

    // gather neighbors: 8 threads per k
    int k = tid >> 3, l8 = tid & 7;
    long long jn;
    if (g_is64) jn = ((const long long*)sidx)[(size_t)n*Kc + k];
    else        jn = (long long)((const int*)sidx)[(size_t)n*Kc + k];
    const float4* src = (const float4*)(x + ((size_t)((b*Sc + (int)jn)*Tc + t)) * Cc);
    #pragma unroll
    for (int q = 0; q < 4; q++) {
        int f4 = l8 + q*8;
        float4 v = src[f4];
        *((float4*)&nb[k][f4*4]) = v;
    }
    if (l8 == 0) {
        nb[k][128] = ali [(size_t)n*Kc + k];
        nb[k][129] = dstp[(size_t)n*Kc + k];
    }
    __syncthreads();

    // logits: thread (k,l8) strides f by 8, reads nb[k][f] once, 4 head partials
    {
        float p0 = 0.f, p1 = 0.f, p2 = 0.f, p3 = 0.f;
        #pragma unroll 4
        for (int f = l8; f < Fc; f += 8) {
            float v = nb[k][f];
            p0 = fmaf(us[0*Fc + f], v, p0);
            p1 = fmaf(us[1*Fc + f], v, p1);
            p2 = fmaf(us[2*Fc + f], v, p2);
            p3 = fmaf(us[3*Fc + f], v, p3);
        }
        #pragma unroll
        for (int o = 4; o >= 1; o >>= 1) {
            p0 += __shfl_xor_sync(0xffffffffu, p0, o, 8);
            p1 += __shfl_xor_sync(0xffffffffu, p1, o, 8);
            p2 += __shfl_xor_sync(0xffffffffu, p2, o, 8);
            p3 += __shfl_xor_sync(0xffffffffu, p3, o, 8);
        }
        if (l8 == 0) { lg[0][k] = p0; lg[1][k] = p1; lg[2][k] = p2; lg[3][k] = p3; }
    }
    __syncthreads();

    // softmax over k (64 threads: h = tid/16, k = tid%16)
    if (tid < Hc*Kc) {
        int h = tid >> 4, kk = tid & 15;
        float lgv = lg[h][kk] + __logf(swgt[(size_t)n*Kc + kk] + 1e-6f);
        float m = lgv;
        #pragma unroll
        for (int o = 8; o >= 1; o >>= 1)
            m = fmaxf(m, __shfl_xor_sync(0xffffffffu, m, o, 16));
        float e = __expf(lgv - m);
        float ssum = e;
        #pragma unroll
        for (int o = 8; o >= 1; o >>= 1)
            ssum += __shfl_xor_sync(0xffffffffu, ssum, o, 16);
        attn_s[h][kk] = e / ssum;
    }
    __syncthreads();

    // nbar: thread = f; read nb[k][f] once, update 4 head accumulators
    for (int f = tid; f < Fc; f += 128) {
        float a0 = 0.f, a1 = 0.f, a2 = 0.f, a3 = 0.f;
        #pragma unroll
        for (int kk = 0; kk < Kc; kk++) {
            float v = nb[kk][f];
            a0 = fmaf(attn_s[0][kk], v, a0);
            a1 = fmaf(attn_s[1][kk], v, a1);
            a2 = fmaf(attn_s[2][kk], v, a2);
            a3 = fmaf(attn_s[3][kk], v, a3);
        }
        float* dst = g_NB + (size_t)n*Uc;
        dst[0*Fc + f] = a0;
        dst[1*Fc + f] = a1;
        dst[2*Fc + f] = a2;
        dst[3*Fc + f] = a3;
    }
}

// ---------------------------------------------------------------------------
// k3: OUT = NB @ W_oT + bp, 16 rows/block as 8 packed row-pairs, 128 threads
// (c' = tid), fma.rn.f32x2 inner math, transpose-on-store.
// ---------------------------------------------------------------------------
__global__ __launch_bounds__(128) void k3_out(const float* __restrict__ bp,
                                              float* __restrict__ out) {
    __shared__ u64 nbs2[Uc*8];   // [j][rp] pair = rows (2rp, 2rp+1); 33.3KB
    int base = blockIdx.x * 16;
    int bt = base / Sc;
    int s0 = base % Sc;
    int b = bt / Tc, t = bt % Tc;
    int tid = threadIdx.x;

    for (int task = tid; task < 8*(Uc/4); task += 128) {
        int rp = task & 7, j4 = task >> 3;        // j4 in 0..129
        const float4* r0 = (const float4*)(g_NB + (size_t)(base + 2*rp)*Uc);
        const float4* r1 = (const float4*)(g_NB + (size_t)(base + 2*rp + 1)*Uc);
        float4 a = r0[j4];
        float4 bb = r1[j4];
        int j = 4*j4;
        nbs2[(j+0)*8 + rp] = pack2(a.x, bb.x);
        nbs2[(j+1)*8 + rp] = pack2(a.y, bb.y);
        nbs2[(j+2)*8 + rp] = pack2(a.z, bb.z);
        nbs2[(j+3)*8 + rp] = pack2(a.w, bb.w);
    }
    __syncthreads();

    int cp = tid;  // 0..127
    u64 acc[8];
    #pragma unroll
    for (int rp = 0; rp < 8; rp++) acc[rp] = pack2(0.f, 0.f);
    #pragma unroll 4
    for (int j = 0; j < Uc; j++) {
        float w = g_WoT[j*Cc + cp];
        u64 wp = pack2(w, w);
        #pragma unroll
        for (int rp = 0; rp < 8; rp++)
            fma2(acc[rp], nbs2[j*8 + rp], wp);
    }
    float bias = bp[cp];
    #pragma unroll
    for (int rp = 0; rp < 8; rp++) {
        float lo, hi;
        unpack2(acc[rp], lo, hi);
        int s = s0 + 2*rp;
        out[((size_t)((b*Sc + s    )*Tc + t))*Cc + cp] = lo + bias;
        out[((size_t)((b*Sc + s + 1)*Tc + t))*Cc + cp] = hi + bias;
    }
}

// ---------------------------------------------------------------------------
extern "C" void kernel_launch(void* const* d_in, const int* in_sizes, int n_in,
                              void* d_out, int out_size) {
    const float* x    = (const float*)d_in[0];
    const void*  sidx = d_in[1];
    const float* swgt = (const float*)d_in[2];
    const float* ali  = (const float*)d_in[3];
    const float* dstp = (const float*)d_in[4];
    const float* Wq   = (const float*)d_in[5];
    const float* Wk   = (const float*)d_in[6];
    const float* Wv   = (const float*)d_in[7];
    const float* Wp   = (const float*)d_in[8];
    const float* bp   = (const float*)d_in[9];
    float* out = (float*)d_out;

    k_detect<<<1, 256>>>((const unsigned int*)sidx);
    k0_combine<<<(Cc*Uc + 255)/256, 256>>>(Wq, Wk, Wv, Wp);
    k1_u<<<Nc/32, 544>>>(x);
    k2_attn<<<Nc, 128>>>(x, sidx, swgt, ali, dstp);
    k3_out<<<Nc/16, 128>>>(bp, out);
}